// round 10
// baseline (speedup 1.0000x reference)
#include <cuda_runtime.h>

#define KA    9
#define HH    240
#define WW    240
#define HW    57600
#define NTOT  518400
#define WK    2160
#define PRE   6000
#define POST  300
#define CAP   8192
#define NB    65536
#define CHK   9
#define MROW  2048            // matrix-covered candidates
#define MW    64              // words per row (MROW/32)
#define MATBLK 2048
#define RST   37              // reset words per block: 2048*37 = 75776 >= NB+CAP+1

__device__ __align__(16) unsigned  g_hist[NB];    // zero invariant
__device__ unsigned                g_cnt;         // zero invariant
__device__ unsigned                g_rank[CAP];   // zero invariant
__device__ unsigned                g_tick0;       // zero invariant (hist ticket)
__device__ unsigned                g_tick1;       // zero invariant (mat ticket)
__device__ int                     g_bound;
__device__ unsigned long long      g_cand[CAP];
__device__ float                   g_sc[PRE];
__device__ float4                  g_boxes[PRE];
__device__ __align__(16) unsigned  g_mat[MROW * MW];

__device__ __forceinline__ unsigned mono(float f) {
    unsigned b = __float_as_uint(f);
    return (b & 0x80000000u) ? ~b : (b | 0x80000000u);
}
__device__ __forceinline__ float unmono(unsigned m) {
    unsigned b = (m & 0x80000000u) ? (m ^ 0x80000000u) : ~m;
    return __uint_as_float(b);
}
__device__ __forceinline__ float box_area(float4 b) {
    return __fmul_rn(fmaxf(b.z - b.x, 0.0f), fmaxf(b.w - b.y, 0.0f));
}
__device__ __forceinline__ bool iou_gt(float4 a, float areaA, float4 b, float areaB) {
    float lx = fmaxf(a.x, b.x);
    float ly = fmaxf(a.y, b.y);
    float rx = fminf(a.z, b.z);
    float ry = fminf(a.w, b.w);
    float iw = fmaxf(rx - lx, 0.0f);
    float ih = fmaxf(ry - ly, 0.0f);
    float inter = __fmul_rn(iw, ih);
    float uni = fmaxf(__fsub_rn(__fadd_rn(areaA, areaB), inter), 1e-9f);
    return __fdiv_rn(inter, uni) > 0.6f;
}

// ---- 1: histogram; last block computes the rank-PRE boundary bucket -----
__global__ __launch_bounds__(1024) void k_hist(const float* __restrict__ cls) {
    int i = blockIdx.x * 1024 + threadIdx.x;
    if (i < NTOT) {
        int k = i / HW;
        int r = i - k * HW;
        atomicAdd(&g_hist[mono(__ldg(&cls[(2 * k) * HW + r])) >> 16], 1u);
    }
    __threadfence();
    __shared__ bool last;
    if (threadIdx.x == 0)
        last = (atomicAdd(&g_tick0, 1u) == gridDim.x - 1);
    __syncthreads();
    if (!last) return;
    if (threadIdx.x == 0) g_tick0 = 0u;          // restore invariant

    __shared__ int ws[32];
    int tid = threadIdx.x;
    const uint4* h4 = (const uint4*)g_hist;
    int base4 = tid * 16;
    int sum = 0;
    #pragma unroll
    for (int j = 0; j < 16; ++j) {
        uint4 v = __ldcg(&h4[base4 + j]);
        sum += (int)(v.x + v.y + v.z + v.w);
    }
    int lane = tid & 31, warp = tid >> 5;
    int sfx = sum;
    #pragma unroll
    for (int d = 1; d < 32; d <<= 1) {
        int v = __shfl_down_sync(0xFFFFFFFFu, sfx, d);
        if (lane < 32 - d) sfx += v;
    }
    if (lane == 0) ws[warp] = sfx;
    __syncthreads();
    int tail = 0;
    for (int w2 = warp + 1; w2 < 32; ++w2) tail += ws[w2];
    int St  = sfx + tail;
    int Snx = St - sum;
    if (St >= PRE && Snx < PRE) {
        int running = Snx;
        int base = tid * 64;
        int B = base;
        for (int j = 63; j >= 0; --j) {
            running += (int)__ldcg(&g_hist[base + j]);
            if (running >= PRE) { B = base + j; break; }
        }
        g_bound = B;
    }
}

// ---- 2: compact candidates >= bound -------------------------------------
__global__ void k_compact(const float* __restrict__ cls) {
    int i = blockIdx.x * blockDim.x + threadIdx.x;
    if (i >= NTOT) return;
    int k = i / HW;
    int r = i - k * HW;
    float s = __ldg(&cls[(2 * k) * HW + r]);
    unsigned key = mono(s);
    if ((int)(key >> 16) >= g_bound) {
        unsigned pos = atomicAdd(&g_cnt, 1u);
        if (pos < CAP)
            g_cand[pos] = ((unsigned long long)key << 20)
                        | (unsigned)((~(unsigned)i) & 0xFFFFFu);
    }
}

// ---- 3: exact descending ranks by counting (144 tile blocks) ------------
__global__ __launch_bounds__(1024) void k_rank() {
    __shared__ unsigned long long sk[1024];
    unsigned n = g_cnt; if (n > CAP) n = CAP;
    int csz = ((int)n + CHK - 1) / CHK;
    int w = blockIdx.x;
    int g = w / CHK, c = w % CHK;
    int c0 = c * csz;
    int c1 = c0 + csz; if (c1 > (int)n) c1 = (int)n;
    int clen = c1 - c0;
    for (int j = threadIdx.x; j < clen; j += 1024) sk[j] = g_cand[c0 + j];
    __syncthreads();
    int ci = g * 512 + (threadIdx.x & 511);
    int h  = threadIdx.x >> 9;
    if (ci < (int)n && clen > 0) {
        unsigned long long my = g_cand[ci];
        int half = (clen + 1) >> 1;
        int j0 = h * half;
        int j1 = j0 + half; if (j1 > clen) j1 = clen;
        int cnt = 0;
        #pragma unroll 8
        for (int j = j0; j < j1; ++j) cnt += (sk[j] > my);
        if (cnt) atomicAdd(&g_rank[ci], (unsigned)cnt);
    }
}

// ---- 4: scatter by rank + box decode/clip -------------------------------
__global__ void k_scatter(const float* __restrict__ deltas,
                          const float* __restrict__ anchors) {
    int i = blockIdx.x * blockDim.x + threadIdx.x;
    unsigned n = g_cnt; if (n > CAP) n = CAP;
    if (i >= (int)n) return;
    unsigned r = g_rank[i];
    if (r >= PRE) return;
    unsigned long long cv = g_cand[i];
    int idx = (int)((~(unsigned)cv) & 0xFFFFFu);
    g_sc[r] = unmono((unsigned)(cv >> 20));
    int hp = idx / WK;
    int t  = idx - hp * WK;
    int wp = t / KA;
    int kp = t - wp * KA;
    float v[4];
    #pragma unroll
    for (int j = 0; j < 4; ++j) {
        int F   = ((kp * 4 + j) * HH + hp) * WW + wp;
        int j2  = F & 3;
        int F4  = F >> 2;
        int k2  = F4 % KA;
        int rem = F4 / KA;
        int w2  = rem % WW;
        int h2  = rem / WW;
        float a = __ldg(&anchors[((h2 * WW + w2) * KA + k2) * 4 + j2]);
        float d = __ldg(&deltas[(k2 * 4 + j2) * HW + h2 * WW + w2]);
        v[j] = fminf(fmaxf(a + d, 0.0f), 1920.0f);
    }
    g_boxes[r] = make_float4(v[0], v[1], v[2], v[3]);
}

// ---- 5: bit-matrix; every block resets an invariant slice; last block
//         runs the greedy sweep + fallback + output -----------------------
__global__ __launch_bounds__(1024) void k_matnms(float* __restrict__ out) {
    int tid = threadIdx.x, lane = tid & 31, warp = tid >> 5;

    // (a) matrix row for candidate blockIdx.x
    {
        int i = blockIdx.x;
        float4 bi = g_boxes[i];
        float  ai = box_area(bi);
        int j0 = tid;
        int j1 = j0 + 1024;
        float4 b0 = g_boxes[j0];
        float4 b1 = g_boxes[j1];
        bool s0 = iou_gt(bi, ai, b0, box_area(b0));
        bool s1 = iou_gt(bi, ai, b1, box_area(b1));
        unsigned w0 = __ballot_sync(0xFFFFFFFFu, s0);
        unsigned w1 = __ballot_sync(0xFFFFFFFFu, s1);
        if (lane == 0) {
            int w = j0 >> 5;
            g_mat[i * MW + w]      = w0;
            g_mat[i * MW + w + 32] = w1;
        }
    }

    // (b) restore zero invariants (hist/rank/cnt dead now): RST words/block
    //     coverage: MATBLK*RST = 75776 >= NB + CAP + 1 = 73729
    {
        int base = blockIdx.x * RST + tid;
        if (tid < RST) {
            if (base < NB)               g_hist[base] = 0u;
            else if (base < NB + CAP)    g_rank[base - NB] = 0u;
            else if (base == NB + CAP)   g_cnt = 0u;
        }
    }

    // (c) ticket: last block does the sweep
    __threadfence();
    __shared__ bool last;
    if (tid == 0) last = (atomicAdd(&g_tick1, 1u) == gridDim.x - 1);
    __syncthreads();
    if (!last) return;
    if (tid == 0) g_tick1 = 0u;

    __shared__ __align__(16) unsigned rowbuf[32 * MW];   // 8 KB chunk of rows
    __shared__ int      s_kidx[POST];
    __shared__ int      s_nk;
    __shared__ float4   kbox[POST];
    __shared__ float    karea[POST];
    __shared__ float4   bb[32];
    __shared__ float    ba[32];
    __shared__ unsigned s_sup;

    if (warp == 0) {
        unsigned m0 = 0u, m1 = 0u;                // lane owns future-mask words 2*lane, 2*lane+1
        int nk = 0;
        for (int c = 0; c < MW && nk < POST; ++c) {
            const uint4* src = (const uint4*)&g_mat[(c << 5) * MW];
            uint4* dst = (uint4*)rowbuf;
            #pragma unroll
            for (int q = 0; q < 16; ++q) dst[lane + 32 * q] = __ldcg(&src[lane + 32 * q]);
            __syncwarp();
            // cur = merged suppression word for this chunk, replicated in every lane
            unsigned cur = __shfl_sync(0xFFFFFFFFu, (c & 1) ? m1 : m0, c >> 1);
            unsigned alive = ~cur;
            while (alive && nk < POST) {
                int l = __ffs(alive) - 1;
                if (lane == 0) s_kidx[nk] = (c << 5) + l;
                ++nk;
                cur |= rowbuf[l * MW + c];                 // broadcast LDS — no shfl
                m0  |= rowbuf[l * MW + 2 * lane];
                m1  |= rowbuf[l * MW + 2 * lane + 1];
                alive = (~cur) & ~((2u << l) - 1u);        // unsuppressed, index > l
            }
            __syncwarp();
        }
        if (lane == 0) s_nk = nk;
    }
    __syncthreads();
    int nk = s_nk;

    // fallback past MROW (rare): lazy 32-wide batches
    if (nk < POST) {
        for (int p = tid; p < nk; p += 1024) {
            float4 b = g_boxes[s_kidx[p]];
            kbox[p] = b; karea[p] = box_area(b);
        }
        if (tid == 0) s_sup = 0u;
        __syncthreads();
        for (int base = MROW; base < PRE && nk < POST; base += 32) {
            int rem = PRE - base; if (rem > 32) rem = 32;
            if (tid < rem) {
                float4 b = g_boxes[base + tid];
                bb[tid] = b; ba[tid] = box_area(b);
            }
            __syncthreads();
            int total = nk << 5;
            for (int idx2 = tid; idx2 < total; idx2 += 1024) {
                int cc = idx2 & 31;
                if (cc < rem && !((s_sup >> cc) & 1u)) {
                    int k = idx2 >> 5;
                    if (iou_gt(kbox[k], karea[k], bb[cc], ba[cc]))
                        atomicOr(&s_sup, 1u << cc);
                }
            }
            __syncthreads();
            if (tid < 32) {
                unsigned valid = (rem >= 32) ? 0xFFFFFFFFu : ((1u << rem) - 1u);
                unsigned alive = (~s_sup) & valid;
                float4 myb = bb[(lane < rem) ? lane : 0];
                float  mya = ba[(lane < rem) ? lane : 0];
                int nk2 = nk;
                while (alive && nk2 < POST) {
                    int l = __ffs((int)alive) - 1;
                    alive &= ~(1u << l);
                    float4 kb;
                    kb.x = __shfl_sync(0xFFFFFFFFu, myb.x, l);
                    kb.y = __shfl_sync(0xFFFFFFFFu, myb.y, l);
                    kb.z = __shfl_sync(0xFFFFFFFFu, myb.z, l);
                    kb.w = __shfl_sync(0xFFFFFFFFu, myb.w, l);
                    float ka_ = __shfl_sync(0xFFFFFFFFu, mya, l);
                    if (lane == 0) { kbox[nk2] = kb; karea[nk2] = ka_; s_kidx[nk2] = base + l; }
                    ++nk2;
                    if (nk2 >= POST) break;
                    bool sup = false;
                    if (alive & (1u << lane)) sup = iou_gt(kb, ka_, myb, mya);
                    alive &= ~__ballot_sync(0xFFFFFFFFu, sup);
                }
                if (lane == 0) { s_nk = nk2; s_sup = 0u; }
            }
            __syncthreads();
            nk = s_nk;
        }
    }

    // output [1, POST, 5]; pad with candidate 0 (nonzero fill_value=0)
    for (int p = tid; p < POST; p += 1024) {
        int q = (p < nk) ? s_kidx[p] : 0;
        float4 b = g_boxes[q];
        out[p * 5 + 0] = g_sc[q];
        out[p * 5 + 1] = b.x;
        out[p * 5 + 2] = b.y;
        out[p * 5 + 3] = b.z;
        out[p * 5 + 4] = b.w;
    }
}

// ---------------------------------------------------------------- launcher
extern "C" void kernel_launch(void* const* d_in, const int* in_sizes, int n_in,
                              void* d_out, int out_size) {
    const float* cls     = (const float*)d_in[0];
    const float* deltas  = (const float*)d_in[1];
    const float* anchors = (const float*)d_in[2];
    float* out = (float*)d_out;

    k_hist   <<<(NTOT + 1023) / 1024, 1024>>>(cls);
    k_compact<<<(NTOT + 255) / 256, 256>>>(cls);
    k_rank   <<<144, 1024>>>();
    k_scatter<<<(CAP + 255) / 256, 256>>>(deltas, anchors);
    k_matnms <<<MATBLK, 1024>>>(out);
}

// round 11
// speedup vs baseline: 1.3927x; 1.3927x over previous
#include <cuda_runtime.h>

#define KA    9
#define HH    240
#define WW    240
#define HW    57600
#define NTOT  518400
#define WK    2160
#define PRE   6000
#define POST  300
#define CAP   8192
#define NB    65536
#define CHK   9
#define MROW  2048            // matrix-covered candidates
#define MW    64              // words per row (MROW/32)

__device__ __align__(16) unsigned  g_hist[NB];    // zero invariant
__device__ unsigned                g_cnt;         // zero invariant
__device__ unsigned                g_rank[CAP];   // zero invariant
__device__ int                     g_bound;
__device__ unsigned long long      g_cand[CAP];
__device__ float                   g_sc[PRE];
__device__ float4                  g_boxes[PRE];
__device__ __align__(16) unsigned  g_mat[MROW * MW];

__device__ __forceinline__ unsigned mono(float f) {
    unsigned b = __float_as_uint(f);
    return (b & 0x80000000u) ? ~b : (b | 0x80000000u);
}
__device__ __forceinline__ float unmono(unsigned m) {
    unsigned b = (m & 0x80000000u) ? (m ^ 0x80000000u) : ~m;
    return __uint_as_float(b);
}
__device__ __forceinline__ float box_area(float4 b) {
    return __fmul_rn(fmaxf(b.z - b.x, 0.0f), fmaxf(b.w - b.y, 0.0f));
}
// exact formula (rel_err 0.0 lineage)
__device__ __forceinline__ bool iou_gt(float4 a, float areaA, float4 b, float areaB) {
    float lx = fmaxf(a.x, b.x);
    float ly = fmaxf(a.y, b.y);
    float rx = fminf(a.z, b.z);
    float ry = fminf(a.w, b.w);
    float iw = fmaxf(rx - lx, 0.0f);
    float ih = fmaxf(ry - ly, 0.0f);
    float inter = __fmul_rn(iw, ih);
    float uni = fmaxf(__fsub_rn(__fadd_rn(areaA, areaB), inter), 1e-9f);
    return __fdiv_rn(inter, uni) > 0.6f;
}
// early-out variant: iw<=0 or ih<=0  =>  inter=0  =>  IoU=0, never >0.6 (exact)
__device__ __forceinline__ bool iou_gt_eo(float4 a, float areaA, float4 b) {
    float lx = fmaxf(a.x, b.x);
    float ly = fmaxf(a.y, b.y);
    float rx = fminf(a.z, b.z);
    float ry = fminf(a.w, b.w);
    float iw = rx - lx;
    float ih = ry - ly;
    if (iw <= 0.0f || ih <= 0.0f) return false;
    float inter = __fmul_rn(iw, ih);
    float areaB = box_area(b);
    float uni = fmaxf(__fsub_rn(__fadd_rn(areaA, areaB), inter), 1e-9f);
    return __fdiv_rn(inter, uni) > 0.6f;
}

__device__ __forceinline__ void cp16(unsigned dst, const void* src) {
    asm volatile("cp.async.cg.shared.global [%0], [%1], 16;" :: "r"(dst), "l"(src));
}

// ---- 1: scores -> 64K-bucket histogram ----------------------------------
__global__ void k_hist(const float* __restrict__ cls) {
    int i = blockIdx.x * blockDim.x + threadIdx.x;
    if (i >= NTOT) return;
    int k = i / HW;
    int r = i - k * HW;
    atomicAdd(&g_hist[mono(__ldg(&cls[(2 * k) * HW + r])) >> 16], 1u);
}

// ---- 2: boundary bucket of rank PRE -------------------------------------
__global__ __launch_bounds__(1024) void k_bound() {
    __shared__ int ws[32];
    int tid = threadIdx.x;
    const uint4* h4 = (const uint4*)g_hist;
    int base4 = tid * 16;
    int sum = 0;
    #pragma unroll
    for (int j = 0; j < 16; ++j) {
        uint4 v = h4[base4 + j];
        sum += (int)(v.x + v.y + v.z + v.w);
    }
    int lane = tid & 31, warp = tid >> 5;
    int sfx = sum;
    #pragma unroll
    for (int d = 1; d < 32; d <<= 1) {
        int v = __shfl_down_sync(0xFFFFFFFFu, sfx, d);
        if (lane < 32 - d) sfx += v;
    }
    if (lane == 0) ws[warp] = sfx;
    __syncthreads();
    int tail = 0;
    for (int w2 = warp + 1; w2 < 32; ++w2) tail += ws[w2];
    int St  = sfx + tail;
    int Snx = St - sum;
    if (St >= PRE && Snx < PRE) {
        int running = Snx;
        int base = tid * 64;
        int B = base;
        for (int j = 63; j >= 0; --j) {
            running += (int)g_hist[base + j];
            if (running >= PRE) { B = base + j; break; }
        }
        g_bound = B;
    }
}

// ---- 3: compact candidates >= bound -------------------------------------
__global__ void k_compact(const float* __restrict__ cls) {
    int i = blockIdx.x * blockDim.x + threadIdx.x;
    if (i >= NTOT) return;
    int k = i / HW;
    int r = i - k * HW;
    float s = __ldg(&cls[(2 * k) * HW + r]);
    unsigned key = mono(s);
    if ((int)(key >> 16) >= g_bound) {
        unsigned pos = atomicAdd(&g_cnt, 1u);
        if (pos < CAP)
            g_cand[pos] = ((unsigned long long)key << 20)
                        | (unsigned)((~(unsigned)i) & 0xFFFFFu);
    }
}

// ---- 4: exact descending ranks by counting (144 tile blocks) ------------
__global__ __launch_bounds__(1024) void k_rank() {
    __shared__ unsigned long long sk[1024];
    unsigned n = g_cnt; if (n > CAP) n = CAP;
    int csz = ((int)n + CHK - 1) / CHK;
    int w = blockIdx.x;
    int g = w / CHK, c = w % CHK;
    int c0 = c * csz;
    int c1 = c0 + csz; if (c1 > (int)n) c1 = (int)n;
    int clen = c1 - c0;
    for (int j = threadIdx.x; j < clen; j += 1024) sk[j] = g_cand[c0 + j];
    __syncthreads();
    int ci = g * 512 + (threadIdx.x & 511);
    int h  = threadIdx.x >> 9;
    if (ci < (int)n && clen > 0) {
        unsigned long long my = g_cand[ci];
        int half = (clen + 1) >> 1;
        int j0 = h * half;
        int j1 = j0 + half; if (j1 > clen) j1 = clen;
        int cnt = 0;
        #pragma unroll 8
        for (int j = j0; j < j1; ++j) cnt += (sk[j] > my);
        if (cnt) atomicAdd(&g_rank[ci], (unsigned)cnt);
    }
}

// ---- 5: scatter by rank + box decode/clip -------------------------------
__global__ void k_scatter(const float* __restrict__ deltas,
                          const float* __restrict__ anchors) {
    int i = blockIdx.x * blockDim.x + threadIdx.x;
    unsigned n = g_cnt; if (n > CAP) n = CAP;
    if (i >= (int)n) return;
    unsigned r = g_rank[i];
    if (r >= PRE) return;
    unsigned long long cv = g_cand[i];
    int idx = (int)((~(unsigned)cv) & 0xFFFFFu);
    g_sc[r] = unmono((unsigned)(cv >> 20));
    int hp = idx / WK;
    int t  = idx - hp * WK;
    int wp = t / KA;
    int kp = t - wp * KA;
    float v[4];
    #pragma unroll
    for (int j = 0; j < 4; ++j) {
        int F   = ((kp * 4 + j) * HH + hp) * WW + wp;
        int j2  = F & 3;
        int F4  = F >> 2;
        int k2  = F4 % KA;
        int rem = F4 / KA;
        int w2  = rem % WW;
        int h2  = rem / WW;
        float a = __ldg(&anchors[((h2 * WW + w2) * KA + k2) * 4 + j2]);
        float d = __ldg(&deltas[(k2 * 4 + j2) * HW + h2 * WW + w2]);
        v[j] = fminf(fmaxf(a + d, 0.0f), 1920.0f);
    }
    g_boxes[r] = make_float4(v[0], v[1], v[2], v[3]);
}

// ---- 6: UPPER-TRIANGLE suppression bit-matrix (early-out IoU) -----------
// row i, word w, bit l set iff j=32w+l > i and IoU(box_i, box_j) > 0.6.
// The sweep only consumes bits j > i, so the lower triangle is written 0.
__global__ __launch_bounds__(1024) void k_mat() {
    int i = blockIdx.x;
    float4 bi = g_boxes[i];
    float  ai = box_area(bi);
    int j0 = threadIdx.x;
    int j1 = j0 + 1024;
    bool s0 = (j0 > i) && iou_gt_eo(bi, ai, g_boxes[j0]);
    bool s1 = (j1 > i) && iou_gt_eo(bi, ai, g_boxes[j1]);
    unsigned w0 = __ballot_sync(0xFFFFFFFFu, s0);
    unsigned w1 = __ballot_sync(0xFFFFFFFFu, s1);
    if ((j0 & 31) == 0) {
        int w = j0 >> 5;
        g_mat[i * MW + w]      = w0;
        g_mat[i * MW + w + 32] = w1;
    }
}

// ---- 7: warp-serial matrix sweep (cp.async double-buffer) + fallback ----
__global__ __launch_bounds__(1024) void k_nms(float* __restrict__ out) {
    __shared__ __align__(16) unsigned rowbuf[2 * 32 * MW];   // 2 x 8 KB ping-pong
    __shared__ int      s_kidx[POST];
    __shared__ int      s_nk;
    __shared__ float4   kbox[POST];
    __shared__ float    karea[POST];
    __shared__ float4   bb[32];
    __shared__ float    ba[32];
    __shared__ unsigned s_sup;
    int tid = threadIdx.x, lane = tid & 31, warp = tid >> 5;

    if (warp == 0) {
        unsigned sbase = (unsigned)__cvta_generic_to_shared(rowbuf) + lane * 16;
        unsigned m0 = 0u, m1 = 0u;            // lane owns future-mask words 2*lane, 2*lane+1
        int nk = 0;

        // prefetch chunk 0 into buffer 0
        {
            const uint4* src = (const uint4*)&g_mat[0];
            #pragma unroll
            for (int q = 0; q < 16; ++q) cp16(sbase + q * 512, src + lane + 32 * q);
            asm volatile("cp.async.commit_group;");
        }
        for (int c = 0; c < MW && nk < POST; ++c) {
            if (c + 1 < MW) {                  // prefetch next chunk into other buffer
                const uint4* src = (const uint4*)&g_mat[((c + 1) << 5) * MW];
                unsigned d = sbase + ((c + 1) & 1) * 8192;
                #pragma unroll
                for (int q = 0; q < 16; ++q) cp16(d + q * 512, src + lane + 32 * q);
                asm volatile("cp.async.commit_group;");
                asm volatile("cp.async.wait_group 1;");
            } else {
                asm volatile("cp.async.wait_group 0;");
            }
            __syncwarp();
            const unsigned* rb = rowbuf + (c & 1) * (32 * MW);

            unsigned cur = __shfl_sync(0xFFFFFFFFu, (c & 1) ? m1 : m0, c >> 1);
            unsigned alive = ~cur;
            while (alive && nk < POST) {
                int l = __ffs(alive) - 1;
                if (lane == 0) s_kidx[nk] = (c << 5) + l;
                ++nk;
                cur |= rb[l * MW + c];                 // broadcast LDS
                m0  |= rb[l * MW + 2 * lane];
                m1  |= rb[l * MW + 2 * lane + 1];
                alive = (~cur) & ~((2u << l) - 1u);    // unsuppressed, index > l
            }
            __syncwarp();
        }
        asm volatile("cp.async.wait_group 0;");        // drain pending copies
        if (lane == 0) s_nk = nk;
    }
    __syncthreads();
    int nk = s_nk;

    // fallback past MROW (rare): lazy 32-wide batches
    if (nk < POST) {
        for (int p = tid; p < nk; p += 1024) {
            float4 b = g_boxes[s_kidx[p]];
            kbox[p] = b; karea[p] = box_area(b);
        }
        if (tid == 0) s_sup = 0u;
        __syncthreads();
        for (int base = MROW; base < PRE && nk < POST; base += 32) {
            int rem = PRE - base; if (rem > 32) rem = 32;
            if (tid < rem) {
                float4 b = g_boxes[base + tid];
                bb[tid] = b; ba[tid] = box_area(b);
            }
            __syncthreads();
            int total = nk << 5;
            for (int idx2 = tid; idx2 < total; idx2 += 1024) {
                int cc = idx2 & 31;
                if (cc < rem && !((s_sup >> cc) & 1u)) {
                    int k = idx2 >> 5;
                    if (iou_gt(kbox[k], karea[k], bb[cc], ba[cc]))
                        atomicOr(&s_sup, 1u << cc);
                }
            }
            __syncthreads();
            if (tid < 32) {
                unsigned valid = (rem >= 32) ? 0xFFFFFFFFu : ((1u << rem) - 1u);
                unsigned alive = (~s_sup) & valid;
                float4 myb = bb[(lane < rem) ? lane : 0];
                float  mya = ba[(lane < rem) ? lane : 0];
                int nk2 = nk;
                while (alive && nk2 < POST) {
                    int l = __ffs((int)alive) - 1;
                    alive &= ~(1u << l);
                    float4 kb;
                    kb.x = __shfl_sync(0xFFFFFFFFu, myb.x, l);
                    kb.y = __shfl_sync(0xFFFFFFFFu, myb.y, l);
                    kb.z = __shfl_sync(0xFFFFFFFFu, myb.z, l);
                    kb.w = __shfl_sync(0xFFFFFFFFu, myb.w, l);
                    float ka_ = __shfl_sync(0xFFFFFFFFu, mya, l);
                    if (lane == 0) { kbox[nk2] = kb; karea[nk2] = ka_; s_kidx[nk2] = base + l; }
                    ++nk2;
                    if (nk2 >= POST) break;
                    bool sup = false;
                    if (alive & (1u << lane)) sup = iou_gt(kb, ka_, myb, mya);
                    alive &= ~__ballot_sync(0xFFFFFFFFu, sup);
                }
                if (lane == 0) { s_nk = nk2; s_sup = 0u; }
            }
            __syncthreads();
            nk = s_nk;
        }
    }

    // output [1, POST, 5]; pad with candidate 0 (nonzero fill_value=0)
    for (int p = tid; p < POST; p += 1024) {
        int q = (p < nk) ? s_kidx[p] : 0;
        float4 b = g_boxes[q];
        out[p * 5 + 0] = g_sc[q];
        out[p * 5 + 1] = b.x;
        out[p * 5 + 2] = b.y;
        out[p * 5 + 3] = b.z;
        out[p * 5 + 4] = b.w;
    }
}

// ---- 8: restore zero invariants for next launch -------------------------
__global__ void k_reset() {
    int i = blockIdx.x * blockDim.x + threadIdx.x;
    if (i < NB)  g_hist[i] = 0u;
    if (i < CAP) g_rank[i] = 0u;
    if (i == 0)  g_cnt = 0u;
}

// ---------------------------------------------------------------- launcher
extern "C" void kernel_launch(void* const* d_in, const int* in_sizes, int n_in,
                              void* d_out, int out_size) {
    const float* cls     = (const float*)d_in[0];
    const float* deltas  = (const float*)d_in[1];
    const float* anchors = (const float*)d_in[2];
    float* out = (float*)d_out;

    k_hist   <<<(NTOT + 255) / 256, 256>>>(cls);
    k_bound  <<<1, 1024>>>();
    k_compact<<<(NTOT + 255) / 256, 256>>>(cls);
    k_rank   <<<144, 1024>>>();
    k_scatter<<<(CAP + 255) / 256, 256>>>(deltas, anchors);
    k_mat    <<<MROW, 1024>>>();
    k_nms    <<<1, 1024>>>(out);
    k_reset  <<<(NB + 255) / 256, 256>>>();
}